// round 1
// baseline (speedup 1.0000x reference)
#include <cuda_runtime.h>

// Problem constants (shapes are fixed by the dataset; sizes are also re-derived
// from in_sizes defensively).
#define D 128          // NODE_DIM == EMBED_DIM == OUT_DIM
#define BM 64          // rows per GEMM block

// Scratch (no allocations allowed -> __device__ globals)
__device__ float g_Wvo[D * D];          // W_v @ W_o, fused projection
__device__ float g_c1[D];               // b_v @ W_o + b_o
__device__ unsigned char g_mask[50000]; // indeg(v) > 0

__global__ void k_mask_zero(int V) {
    int i = blockIdx.x * blockDim.x + threadIdx.x;
    if (i < V) g_mask[i] = 0;
}

__global__ void k_mask_scatter(const int* __restrict__ ei, int E) {
    int e = blockIdx.x * blockDim.x + threadIdx.x;
    if (e < E) g_mask[ei[E + e]] = 1;  // dest row of edge_index; benign same-value race
}

// W_vo[i][j] = sum_k W_v[i][k] * W_o[k][j];  c1[j] = sum_k b_v[k]*W_o[k][j] + b_o[j]
__global__ void k_prep(const float* __restrict__ Wv, const float* __restrict__ Wo,
                       const float* __restrict__ bv, const float* __restrict__ bo) {
    int idx = blockIdx.x * blockDim.x + threadIdx.x;  // 16384 threads
    int i = idx >> 7, j = idx & 127;
    float s = 0.f;
    #pragma unroll 8
    for (int k = 0; k < D; k++) s = fmaf(Wv[i * D + k], Wo[k * D + j], s);
    g_Wvo[idx] = s;
    if (i == 0) {
        float c = bo[j];
        for (int k = 0; k < D; k++) c = fmaf(bv[k], Wo[k * D + j], c);
        g_c1[j] = c;
    }
}

// out[v,:] = mask[v] ? node_feats[v,:] @ W_vo + c1 : b_o
// Block: 256 threads, 64 rows x 128 cols. W_vo (64KB) + A tile (32KB) in dynamic smem.
// Thread tile 8x4. A reads are warp-broadcast LDS.32 (conflict-free); B reads LDS.128.
__global__ __launch_bounds__(256, 2)
void k_gemm(const float* __restrict__ A, const float* __restrict__ bo,
            float* __restrict__ out, int V) {
    extern __shared__ float sm[];
    float* Bs = sm;            // [128][128] = W_vo
    float* Am = sm + D * D;    // [64][128]  = A tile (row-major)
    __shared__ float c1s[D];
    __shared__ float bos[D];
    __shared__ unsigned char ms[BM];

    const int tid = threadIdx.x;
    const int m0 = blockIdx.x * BM;

    // Stage W_vo: 16384 floats = 4096 float4, 16 per thread, coalesced.
    {
        float4* Bs4 = (float4*)Bs;
        const float4* W4 = (const float4*)g_Wvo;
        #pragma unroll
        for (int i = 0; i < 16; i++) Bs4[tid + i * 256] = W4[tid + i * 256];
    }
    // Stage A rows: 64 rows x 32 float4 = 2048 float4, 8 per thread, coalesced.
    #pragma unroll
    for (int i = 0; i < 8; i++) {
        int idx = tid + i * 256;
        int row = idx >> 5;
        int c4  = idx & 31;
        int gm = m0 + row;
        float4 v = make_float4(0.f, 0.f, 0.f, 0.f);
        if (gm < V) v = ((const float4*)A)[(size_t)gm * 32 + c4];
        ((float4*)(Am + row * D))[c4] = v;
    }
    if (tid < D) { c1s[tid] = g_c1[tid]; bos[tid] = bo[tid]; }
    if (tid < BM) { int gm = m0 + tid; ms[tid] = (gm < V) ? g_mask[gm] : (unsigned char)0; }
    __syncthreads();

    const int mi = tid >> 5;       // 0..7  -> rows mi*8 .. mi*8+7
    const int ni = tid & 31;       // 0..31 -> cols ni*4 .. ni*4+3
    const int mrow = mi * 8;
    const int nc = ni * 4;

    float acc[8][4];
    #pragma unroll
    for (int a = 0; a < 8; a++) { acc[a][0] = acc[a][1] = acc[a][2] = acc[a][3] = 0.f; }

    #pragma unroll 8
    for (int k = 0; k < D; k++) {
        float4 b = *(const float4*)(Bs + k * D + nc);
        #pragma unroll
        for (int a = 0; a < 8; a++) {
            float av = Am[(mrow + a) * D + k];   // warp-broadcast
            acc[a][0] = fmaf(av, b.x, acc[a][0]);
            acc[a][1] = fmaf(av, b.y, acc[a][1]);
            acc[a][2] = fmaf(av, b.z, acc[a][2]);
            acc[a][3] = fmaf(av, b.w, acc[a][3]);
        }
    }

    #pragma unroll
    for (int a = 0; a < 8; a++) {
        int gm = m0 + mrow + a;
        if (gm >= V) continue;
        float4 r;
        if (ms[mrow + a]) {
            r.x = acc[a][0] + c1s[nc + 0];
            r.y = acc[a][1] + c1s[nc + 1];
            r.z = acc[a][2] + c1s[nc + 2];
            r.w = acc[a][3] + c1s[nc + 3];
        } else {
            r.x = bos[nc + 0]; r.y = bos[nc + 1]; r.z = bos[nc + 2]; r.w = bos[nc + 3];
        }
        ((float4*)out)[(size_t)gm * 32 + ni] = r;
    }
}

extern "C" void kernel_launch(void* const* d_in, const int* in_sizes, int n_in,
                              void* d_out, int out_size) {
    // Input order per metadata: node_feats, edge_feats, edge_index, W_q, b_q,
    // W_k, b_k, W_v, b_v, W_b, b_b, W_o, b_o
    const float* node = (const float*)d_in[0];
    const int*   ei   = (const int*)d_in[2];
    const float* Wv   = (const float*)d_in[7];
    const float* bv   = (const float*)d_in[8];
    const float* Wo   = (const float*)d_in[11];
    const float* bo   = (const float*)d_in[12];
    float* out = (float*)d_out;

    const int V = in_sizes[0] / D;
    const int E = in_sizes[2] / 2;

    k_mask_zero<<<(V + 255) / 256, 256>>>(V);
    k_mask_scatter<<<(E + 255) / 256, 256>>>(ei, E);
    k_prep<<<64, 256>>>(Wv, Wo, bv, bo);

    const size_t smem = (size_t)(D * D + BM * D) * sizeof(float);  // 96 KB
    cudaFuncSetAttribute(k_gemm, cudaFuncAttributeMaxDynamicSharedMemorySize, (int)smem);
    k_gemm<<<(V + BM - 1) / BM, 256, smem>>>(node, bo, out, V);
}

// round 4
// speedup vs baseline: 1.0278x; 1.0278x over previous
#include <cuda_runtime.h>
#include <cuda_bf16.h>
#include <cstdint>

#define D 128
#define BM 128
#define PAD 136            // bf16 elements per SMEM row (272B = 68 words, 68%32=4 -> conflict-free)

// ---------------- device scratch (no allocations allowed) ----------------
__device__ float g_c1[D];                        // b_v @ W_o + b_o
__device__ unsigned char g_mask[50048];          // indeg(v) > 0
__device__ __align__(16) unsigned short g_Bh[D * D];  // B[n][k] = W_vo[k][n], bf16 hi
__device__ __align__(16) unsigned short g_Bl[D * D];  // residual lo

__device__ __forceinline__ unsigned short bf16h(float x) {
    return __bfloat16_as_ushort(__float2bfloat16(x));
}
__device__ __forceinline__ float bf16f(unsigned short h) {
    return __uint_as_float((uint32_t)h << 16);
}

// ---------------- kernel 1: prep W_vo (split bf16, [n][k]) + c1 + zero mask ----------------
// blocks 0..127: W_vo row b (k-index). blocks >=128: zero mask.
__global__ void k_prep(const float* __restrict__ Wv, const float* __restrict__ Wo,
                       const float* __restrict__ bv, const float* __restrict__ bo, int V) {
    __shared__ float WvS[D];
    int b = blockIdx.x;
    int j = threadIdx.x;           // 128 threads
    if (b >= D) {
        int i = (b - D) * D + j;
        if (i < V) g_mask[i] = 0;
        return;
    }
    WvS[j] = Wv[b * D + j];
    __syncthreads();
    float s = 0.f;
    #pragma unroll 8
    for (int k = 0; k < D; k++) s = fmaf(WvS[k], Wo[k * D + j], s);
    unsigned short h = bf16h(s);
    unsigned short l = bf16h(s - bf16f(h));
    g_Bh[j * D + b] = h;           // B[n=j][k=b]
    g_Bl[j * D + b] = l;
    if (b == 0) {
        float c = bo[j];
        for (int k = 0; k < D; k++) c = fmaf(bv[k], Wo[k * D + j], c);
        g_c1[j] = c;
    }
}

// ---------------- kernel 2: scatter indeg mask (int4-vectorized, scalar tail) ----------------
__global__ void k_mask_scatter(const int* __restrict__ ei, int E) {
    int t = blockIdx.x * blockDim.x + threadIdx.x;
    int E4 = E >> 2;
    if (t < E4) {
        int4 d = ((const int4*)(ei + E))[t];
        g_mask[d.x] = 1; g_mask[d.y] = 1; g_mask[d.z] = 1; g_mask[d.w] = 1;
    } else if (t == E4) {
        for (int e = E4 * 4; e < E; e++) g_mask[ei[E + e]] = 1;
    }
}

// ---------------- kernel 3: HMMA GEMM ----------------
// out[v,:] = mask[v] ? node[v,:] @ W_vo + c1 : b_o
// Split-bf16 3-term: Ah*Bh + Al*Bh + Ah*Bl, fp32 accum via mma.sync m16n8k16.
__global__ __launch_bounds__(256)
void k_gemm_mma(const float* __restrict__ A, const float* __restrict__ bo,
                float* __restrict__ out, int V) {
    extern __shared__ __align__(16) unsigned short sm[];
    unsigned short* Ah = sm;                 // [128][PAD]
    unsigned short* Al = sm + BM * PAD;
    unsigned short* Bh = sm + 2 * BM * PAD;  // [128 n][PAD k]
    unsigned short* Bl = sm + 3 * BM * PAD;
    __shared__ float c1s[D], bos[D];

    const int tid = threadIdx.x;
    const int wid = tid >> 5, lid = tid & 31;
    const int m0 = blockIdx.x * BM;

    // Stage B hi/lo: 2048 uint4 each, coalesced.
    #pragma unroll
    for (int i = 0; i < 8; i++) {
        int idx = tid + i * 256;
        int n = idx >> 4, c = idx & 15;               // c indexes 8-bf16 chunks
        *(uint4*)(Bh + n * PAD + c * 8) = ((const uint4*)g_Bh)[idx];
        *(uint4*)(Bl + n * PAD + c * 8) = ((const uint4*)g_Bl)[idx];
    }
    // Stage A: load fp32, convert to hi/lo bf16. 4096 float4, coalesced.
    #pragma unroll
    for (int i = 0; i < 16; i++) {
        int idx = tid + i * 256;
        int row = idx >> 5, c4 = idx & 31;
        int gm = m0 + row;
        float4 v = make_float4(0.f, 0.f, 0.f, 0.f);
        if (gm < V) v = ((const float4*)A)[(size_t)gm * 32 + c4];
        unsigned short h0 = bf16h(v.x), h1 = bf16h(v.y), h2 = bf16h(v.z), h3 = bf16h(v.w);
        uint2 hp = make_uint2((uint32_t)h0 | ((uint32_t)h1 << 16),
                              (uint32_t)h2 | ((uint32_t)h3 << 16));
        unsigned short l0 = bf16h(v.x - bf16f(h0)), l1 = bf16h(v.y - bf16f(h1));
        unsigned short l2 = bf16h(v.z - bf16f(h2)), l3 = bf16h(v.w - bf16f(h3));
        uint2 lp = make_uint2((uint32_t)l0 | ((uint32_t)l1 << 16),
                              (uint32_t)l2 | ((uint32_t)l3 << 16));
        *(uint2*)(Ah + row * PAD + c4 * 4) = hp;
        *(uint2*)(Al + row * PAD + c4 * 4) = lp;
    }
    if (tid < D) { c1s[tid] = g_c1[tid]; bos[tid] = bo[tid]; }
    __syncthreads();

    // ---- MMA mainloop ----
    const int row0 = wid * 16;
    const int g = lid >> 2, t = lid & 3;
    float acc[16][4];
    #pragma unroll
    for (int n = 0; n < 16; n++) { acc[n][0] = acc[n][1] = acc[n][2] = acc[n][3] = 0.f; }

    for (int p = 0; p < 3; p++) {
        const unsigned short* As_ = (p == 1) ? Al : Ah;
        const unsigned short* Bs_ = (p == 2) ? Bl : Bh;
        const unsigned short* arow0 = As_ + (row0 + g) * PAD + 2 * t;
        const unsigned short* arow1 = As_ + (row0 + g + 8) * PAD + 2 * t;
        const unsigned short* brow = Bs_ + g * PAD + 2 * t;
        #pragma unroll
        for (int kk = 0; kk < 8; kk++) {
            uint32_t a0 = *(const uint32_t*)(arow0 + kk * 16);
            uint32_t a1 = *(const uint32_t*)(arow1 + kk * 16);
            uint32_t a2 = *(const uint32_t*)(arow0 + kk * 16 + 8);
            uint32_t a3 = *(const uint32_t*)(arow1 + kk * 16 + 8);
            #pragma unroll
            for (int n = 0; n < 16; n++) {
                uint32_t b0 = *(const uint32_t*)(brow + n * 8 * PAD + kk * 16);
                uint32_t b1 = *(const uint32_t*)(brow + n * 8 * PAD + kk * 16 + 8);
                asm volatile(
                    "mma.sync.aligned.m16n8k16.row.col.f32.bf16.bf16.f32 "
                    "{%0,%1,%2,%3}, {%4,%5,%6,%7}, {%8,%9}, {%0,%1,%2,%3};"
                    : "+f"(acc[n][0]), "+f"(acc[n][1]), "+f"(acc[n][2]), "+f"(acc[n][3])
                    : "r"(a0), "r"(a1), "r"(a2), "r"(a3), "r"(b0), "r"(b1));
            }
        }
    }
    __syncthreads();   // done reading Ah/Al; reuse as fp32 staging

    // ---- Epilogue: fragments -> SMEM (stride 132 floats), then coalesced masked store ----
    float* Cst = (float*)sm;
    #pragma unroll
    for (int n = 0; n < 16; n++) {
        int c = n * 8 + 2 * t;
        *(float2*)(Cst + (row0 + g) * 132 + c)     = make_float2(acc[n][0], acc[n][1]);
        *(float2*)(Cst + (row0 + g + 8) * 132 + c) = make_float2(acc[n][2], acc[n][3]);
    }
    __syncthreads();
    #pragma unroll
    for (int i = 0; i < 16; i++) {
        int idx = tid + i * 256;
        int row = idx >> 5, c4 = idx & 31;
        int gm = m0 + row;
        if (gm >= V) continue;
        bool msk = g_mask[gm] != 0;
        float4 v = *(const float4*)(Cst + row * 132 + c4 * 4);
        float4 r;
        r.x = msk ? v.x + c1s[c4 * 4 + 0] : bos[c4 * 4 + 0];
        r.y = msk ? v.y + c1s[c4 * 4 + 1] : bos[c4 * 4 + 1];
        r.z = msk ? v.z + c1s[c4 * 4 + 2] : bos[c4 * 4 + 2];
        r.w = msk ? v.w + c1s[c4 * 4 + 3] : bos[c4 * 4 + 3];
        ((float4*)out)[(size_t)gm * 32 + c4] = r;
    }
}

// ---------------- launch ----------------
extern "C" void kernel_launch(void* const* d_in, const int* in_sizes, int n_in,
                              void* d_out, int out_size) {
    const float* node = (const float*)d_in[0];
    const int*   ei   = (const int*)d_in[2];
    const float* Wv   = (const float*)d_in[7];
    const float* bv   = (const float*)d_in[8];
    const float* Wo   = (const float*)d_in[11];
    const float* bo   = (const float*)d_in[12];
    float* out = (float*)d_out;

    const int V = in_sizes[0] / D;
    const int E = in_sizes[2] / 2;

    k_prep<<<D + (V + D - 1) / D, D>>>(Wv, Wo, bv, bo, V);
    k_mask_scatter<<<(E / 4 + 256) / 256, 256>>>(ei, E);

    const int smem = 4 * BM * PAD * 2;   // 139264 B
    cudaFuncSetAttribute(k_gemm_mma, cudaFuncAttributeMaxDynamicSharedMemorySize, smem);
    k_gemm_mma<<<(V + BM - 1) / BM, 256, smem>>>(node, bo, out, V);
}

// round 5
// speedup vs baseline: 1.0291x; 1.0013x over previous
#include <cuda_runtime.h>
#include <cuda_bf16.h>
#include <cstdint>

#define D 128
#define BM 128
#define PAD 136            // bf16 elements per SMEM row (272B = 68 words, 68%32=4 -> conflict-free)

// ---------------- device scratch (no allocations allowed) ----------------
__device__ float g_c1[D];                        // b_v @ W_o + b_o
__device__ unsigned char g_mask[50048];          // indeg(v) > 0
__device__ __align__(16) unsigned short g_Bh[D * D];  // B[n][k] = W_vo[k][n], bf16 hi
__device__ __align__(16) unsigned short g_Bl[D * D];  // residual lo

__device__ __forceinline__ unsigned short bf16h(float x) {
    return __bfloat16_as_ushort(__float2bfloat16(x));
}
__device__ __forceinline__ float bf16f(unsigned short h) {
    return __uint_as_float((uint32_t)h << 16);
}

// ---------------- kernel 1: prep W_vo (split bf16, [n][k]) + c1 + zero mask ----------------
// blocks 0..127: W_vo row b (k-index). blocks >=128: zero mask.
__global__ void k_prep(const float* __restrict__ Wv, const float* __restrict__ Wo,
                       const float* __restrict__ bv, const float* __restrict__ bo, int V) {
    __shared__ float WvS[D];
    int b = blockIdx.x;
    int j = threadIdx.x;           // 128 threads
    if (b >= D) {
        int i = (b - D) * D + j;
        if (i < V) g_mask[i] = 0;
        return;
    }
    WvS[j] = Wv[b * D + j];
    __syncthreads();
    float s = 0.f;
    #pragma unroll 8
    for (int k = 0; k < D; k++) s = fmaf(WvS[k], Wo[k * D + j], s);
    unsigned short h = bf16h(s);
    unsigned short l = bf16h(s - bf16f(h));
    g_Bh[j * D + b] = h;           // B[n=j][k=b]
    g_Bl[j * D + b] = l;
    if (b == 0) {
        float c = bo[j];
        for (int k = 0; k < D; k++) c = fmaf(bv[k], Wo[k * D + j], c);
        g_c1[j] = c;
    }
}

// ---------------- kernel 2: scatter indeg mask (int4-vectorized, scalar tail) ----------------
__global__ void k_mask_scatter(const int* __restrict__ ei, int E) {
    int t = blockIdx.x * blockDim.x + threadIdx.x;
    int E4 = E >> 2;
    if (t < E4) {
        int4 d = ((const int4*)(ei + E))[t];
        g_mask[d.x] = 1; g_mask[d.y] = 1; g_mask[d.z] = 1; g_mask[d.w] = 1;
    } else if (t == E4) {
        for (int e = E4 * 4; e < E; e++) g_mask[ei[E + e]] = 1;
    }
}

// ---------------- kernel 3: HMMA GEMM ----------------
// out[v,:] = mask[v] ? node[v,:] @ W_vo + c1 : b_o
// Split-bf16 3-term: Ah*Bh + Al*Bh + Ah*Bl, fp32 accum via mma.sync m16n8k16.
__global__ __launch_bounds__(256)
void k_gemm_mma(const float* __restrict__ A, const float* __restrict__ bo,
                float* __restrict__ out, int V) {
    extern __shared__ __align__(16) unsigned short sm[];
    unsigned short* Ah = sm;                 // [128][PAD]
    unsigned short* Al = sm + BM * PAD;
    unsigned short* Bh = sm + 2 * BM * PAD;  // [128 n][PAD k]
    unsigned short* Bl = sm + 3 * BM * PAD;
    __shared__ float c1s[D], bos[D];

    const int tid = threadIdx.x;
    const int wid = tid >> 5, lid = tid & 31;
    const int m0 = blockIdx.x * BM;

    // Stage B hi/lo: 2048 uint4 each, coalesced.
    #pragma unroll
    for (int i = 0; i < 8; i++) {
        int idx = tid + i * 256;
        int n = idx >> 4, c = idx & 15;               // c indexes 8-bf16 chunks
        *(uint4*)(Bh + n * PAD + c * 8) = ((const uint4*)g_Bh)[idx];
        *(uint4*)(Bl + n * PAD + c * 8) = ((const uint4*)g_Bl)[idx];
    }
    // Stage A: load fp32, convert to hi/lo bf16. 4096 float4, coalesced.
    #pragma unroll
    for (int i = 0; i < 16; i++) {
        int idx = tid + i * 256;
        int row = idx >> 5, c4 = idx & 31;
        int gm = m0 + row;
        float4 v = make_float4(0.f, 0.f, 0.f, 0.f);
        if (gm < V) v = ((const float4*)A)[(size_t)gm * 32 + c4];
        unsigned short h0 = bf16h(v.x), h1 = bf16h(v.y), h2 = bf16h(v.z), h3 = bf16h(v.w);
        uint2 hp = make_uint2((uint32_t)h0 | ((uint32_t)h1 << 16),
                              (uint32_t)h2 | ((uint32_t)h3 << 16));
        unsigned short l0 = bf16h(v.x - bf16f(h0)), l1 = bf16h(v.y - bf16f(h1));
        unsigned short l2 = bf16h(v.z - bf16f(h2)), l3 = bf16h(v.w - bf16f(h3));
        uint2 lp = make_uint2((uint32_t)l0 | ((uint32_t)l1 << 16),
                              (uint32_t)l2 | ((uint32_t)l3 << 16));
        *(uint2*)(Ah + row * PAD + c4 * 4) = hp;
        *(uint2*)(Al + row * PAD + c4 * 4) = lp;
    }
    if (tid < D) { c1s[tid] = g_c1[tid]; bos[tid] = bo[tid]; }
    __syncthreads();

    // ---- MMA mainloop ----
    const int row0 = wid * 16;
    const int g = lid >> 2, t = lid & 3;
    float acc[16][4];
    #pragma unroll
    for (int n = 0; n < 16; n++) { acc[n][0] = acc[n][1] = acc[n][2] = acc[n][3] = 0.f; }

    for (int p = 0; p < 3; p++) {
        const unsigned short* As_ = (p == 1) ? Al : Ah;
        const unsigned short* Bs_ = (p == 2) ? Bl : Bh;
        const unsigned short* arow0 = As_ + (row0 + g) * PAD + 2 * t;
        const unsigned short* arow1 = As_ + (row0 + g + 8) * PAD + 2 * t;
        const unsigned short* brow = Bs_ + g * PAD + 2 * t;
        #pragma unroll
        for (int kk = 0; kk < 8; kk++) {
            uint32_t a0 = *(const uint32_t*)(arow0 + kk * 16);
            uint32_t a1 = *(const uint32_t*)(arow1 + kk * 16);
            uint32_t a2 = *(const uint32_t*)(arow0 + kk * 16 + 8);
            uint32_t a3 = *(const uint32_t*)(arow1 + kk * 16 + 8);
            #pragma unroll
            for (int n = 0; n < 16; n++) {
                uint32_t b0 = *(const uint32_t*)(brow + n * 8 * PAD + kk * 16);
                uint32_t b1 = *(const uint32_t*)(brow + n * 8 * PAD + kk * 16 + 8);
                asm volatile(
                    "mma.sync.aligned.m16n8k16.row.col.f32.bf16.bf16.f32 "
                    "{%0,%1,%2,%3}, {%4,%5,%6,%7}, {%8,%9}, {%0,%1,%2,%3};"
                    : "+f"(acc[n][0]), "+f"(acc[n][1]), "+f"(acc[n][2]), "+f"(acc[n][3])
                    : "r"(a0), "r"(a1), "r"(a2), "r"(a3), "r"(b0), "r"(b1));
            }
        }
    }
    __syncthreads();   // done reading Ah/Al; reuse as fp32 staging

    // ---- Epilogue: fragments -> SMEM (stride 132 floats), then coalesced masked store ----
    float* Cst = (float*)sm;
    #pragma unroll
    for (int n = 0; n < 16; n++) {
        int c = n * 8 + 2 * t;
        *(float2*)(Cst + (row0 + g) * 132 + c)     = make_float2(acc[n][0], acc[n][1]);
        *(float2*)(Cst + (row0 + g + 8) * 132 + c) = make_float2(acc[n][2], acc[n][3]);
    }
    __syncthreads();
    #pragma unroll
    for (int i = 0; i < 16; i++) {
        int idx = tid + i * 256;
        int row = idx >> 5, c4 = idx & 31;
        int gm = m0 + row;
        if (gm >= V) continue;
        bool msk = g_mask[gm] != 0;
        float4 v = *(const float4*)(Cst + row * 132 + c4 * 4);
        float4 r;
        r.x = msk ? v.x + c1s[c4 * 4 + 0] : bos[c4 * 4 + 0];
        r.y = msk ? v.y + c1s[c4 * 4 + 1] : bos[c4 * 4 + 1];
        r.z = msk ? v.z + c1s[c4 * 4 + 2] : bos[c4 * 4 + 2];
        r.w = msk ? v.w + c1s[c4 * 4 + 3] : bos[c4 * 4 + 3];
        ((float4*)out)[(size_t)gm * 32 + c4] = r;
    }
}

// ---------------- launch ----------------
extern "C" void kernel_launch(void* const* d_in, const int* in_sizes, int n_in,
                              void* d_out, int out_size) {
    const float* node = (const float*)d_in[0];
    const int*   ei   = (const int*)d_in[2];
    const float* Wv   = (const float*)d_in[7];
    const float* bv   = (const float*)d_in[8];
    const float* Wo   = (const float*)d_in[11];
    const float* bo   = (const float*)d_in[12];
    float* out = (float*)d_out;

    const int V = in_sizes[0] / D;
    const int E = in_sizes[2] / 2;

    k_prep<<<D + (V + D - 1) / D, D>>>(Wv, Wo, bv, bo, V);
    k_mask_scatter<<<(E / 4 + 256) / 256, 256>>>(ei, E);

    const int smem = 4 * BM * PAD * 2;   // 139264 B
    cudaFuncSetAttribute(k_gemm_mma, cudaFuncAttributeMaxDynamicSharedMemorySize, smem);
    k_gemm_mma<<<(V + BM - 1) / BM, 256, smem>>>(node, bo, out, V);
}

// round 6
// speedup vs baseline: 1.2064x; 1.1723x over previous
#include <cuda_runtime.h>
#include <cuda_bf16.h>
#include <cstdint>

#define D 128
#define BM 128
#define PAD 136            // bf16 elements per SMEM row (272B = 68 words, 68%32=4 -> conflict-free)
#define MASK_BYTES 50048   // V rounded up, 3128 int4

// ---------------- device scratch (no allocations allowed) ----------------
__device__ float g_c1[D];                        // b_v @ W_o + b_o
__device__ unsigned char g_mask[MASK_BYTES];     // indeg(v) > 0
__device__ __align__(16) unsigned short g_Bh[D * D];  // B[n][k] = W_vo[k][n], bf16 hi
__device__ __align__(16) unsigned short g_Bl[D * D];  // residual lo

__device__ __forceinline__ unsigned short bf16h(float x) {
    return __bfloat16_as_ushort(__float2bfloat16(x));
}
__device__ __forceinline__ float bf16f(unsigned short h) {
    return __uint_as_float((uint32_t)h << 16);
}

// ---------------- kernel 1: prep W_vo (split bf16, [n][k]) + c1 + zero mask ----------------
// Blocks 0..15: Wo staged in 64KB smem; block b computes i-rows [8b, 8b+8).
// Blocks 16..28: vectorized mask zero.
__global__ void k_prep(const float* __restrict__ Wv, const float* __restrict__ Wo,
                       const float* __restrict__ bv, const float* __restrict__ bo) {
    extern __shared__ float WoS[];                // [128][128]
    __shared__ float WvS[8 * D];
    const int tid = threadIdx.x;
    const int b = blockIdx.x;
    if (b >= 16) {                                // mask-zero portion
        int idx = (b - 16) * 256 + tid;
        if (idx < MASK_BYTES / 16) ((int4*)g_mask)[idx] = make_int4(0, 0, 0, 0);
        return;
    }
    // Stage Wo: 4096 float4 / 256 thr = 16 each, coalesced.
    #pragma unroll
    for (int i = 0; i < 16; i++)
        ((float4*)WoS)[tid + i * 256] = ((const float4*)Wo)[tid + i * 256];
    // Stage the 8 Wv rows this block needs: 1024 floats = 256 float4.
    ((float4*)WvS)[tid] = ((const float4*)(Wv + b * 8 * D))[tid];
    __syncthreads();

    const int j = tid & 127;                      // output column (n index)
    const int ip = tid >> 7;                      // 0..1 -> i-rows {4ip..4ip+3}
    float acc0 = 0.f, acc1 = 0.f, acc2 = 0.f, acc3 = 0.f;
    #pragma unroll 16
    for (int k = 0; k < D; k++) {
        float w = WoS[k * D + j];
        acc0 = fmaf(WvS[(ip * 4 + 0) * D + k], w, acc0);   // broadcast LDS
        acc1 = fmaf(WvS[(ip * 4 + 1) * D + k], w, acc1);
        acc2 = fmaf(WvS[(ip * 4 + 2) * D + k], w, acc2);
        acc3 = fmaf(WvS[(ip * 4 + 3) * D + k], w, acc3);
    }
    float a[4] = {acc0, acc1, acc2, acc3};
    #pragma unroll
    for (int c = 0; c < 4; c++) {
        int i = b * 8 + ip * 4 + c;               // k index of W_vo
        unsigned short h = bf16h(a[c]);
        unsigned short l = bf16h(a[c] - bf16f(h));
        g_Bh[j * D + i] = h;                      // B[n=j][k=i]
        g_Bl[j * D + i] = l;
    }
    if (b == 0 && ip == 0) {
        float c = bo[j];
        #pragma unroll 16
        for (int k = 0; k < D; k++) c = fmaf(bv[k], WoS[k * D + j], c);
        g_c1[j] = c;
    }
}

// ---------------- kernel 2: scatter indeg mask (int4-vectorized, scalar tail) ----------------
__global__ void k_mask_scatter(const int* __restrict__ ei, int E) {
    int t = blockIdx.x * blockDim.x + threadIdx.x;
    int E4 = E >> 2;
    if (t < E4) {
        int4 d = ((const int4*)(ei + E))[t];
        g_mask[d.x] = 1; g_mask[d.y] = 1; g_mask[d.z] = 1; g_mask[d.w] = 1;
    } else if (t == E4) {
        for (int e = E4 * 4; e < E; e++) g_mask[ei[E + e]] = 1;
    }
}

// ---------------- kernel 3: HMMA GEMM ----------------
// out[v,:] = mask[v] ? node[v,:] @ W_vo + c1 : b_o
// Split-bf16 3-term: Ah*Bh + Al*Bh + Ah*Bl, fp32 accum via mma.sync m16n8k16.
// Fused mainloop: per k-step load A hi+lo frags once, then per-n load Bh/Bl and
// issue all three MMAs (LDS count 576/warp vs 864 for 3 sequential passes).
__global__ __launch_bounds__(256, 1)
void k_gemm_mma(const float* __restrict__ A, const float* __restrict__ bo,
                float* __restrict__ out, int V) {
    extern __shared__ __align__(16) unsigned short sm[];
    unsigned short* Ah = sm;                 // [128][PAD]
    unsigned short* Al = sm + BM * PAD;
    unsigned short* Bh = sm + 2 * BM * PAD;  // [128 n][PAD k]
    unsigned short* Bl = sm + 3 * BM * PAD;
    __shared__ float c1s[D], bos[D];

    const int tid = threadIdx.x;
    const int wid = tid >> 5, lid = tid & 31;
    const int m0 = blockIdx.x * BM;

    // Stage B hi/lo: 2048 uint4 each, coalesced.
    #pragma unroll
    for (int i = 0; i < 8; i++) {
        int idx = tid + i * 256;
        int n = idx >> 4, c = idx & 15;               // c indexes 8-bf16 chunks
        *(uint4*)(Bh + n * PAD + c * 8) = ((const uint4*)g_Bh)[idx];
        *(uint4*)(Bl + n * PAD + c * 8) = ((const uint4*)g_Bl)[idx];
    }
    // Stage A: load fp32, convert to hi/lo bf16. 4096 float4, coalesced.
    #pragma unroll
    for (int i = 0; i < 16; i++) {
        int idx = tid + i * 256;
        int row = idx >> 5, c4 = idx & 31;
        int gm = m0 + row;
        float4 v = make_float4(0.f, 0.f, 0.f, 0.f);
        if (gm < V) v = ((const float4*)A)[(size_t)gm * 32 + c4];
        unsigned short h0 = bf16h(v.x), h1 = bf16h(v.y), h2 = bf16h(v.z), h3 = bf16h(v.w);
        uint2 hp = make_uint2((uint32_t)h0 | ((uint32_t)h1 << 16),
                              (uint32_t)h2 | ((uint32_t)h3 << 16));
        unsigned short l0 = bf16h(v.x - bf16f(h0)), l1 = bf16h(v.y - bf16f(h1));
        unsigned short l2 = bf16h(v.z - bf16f(h2)), l3 = bf16h(v.w - bf16f(h3));
        uint2 lp = make_uint2((uint32_t)l0 | ((uint32_t)l1 << 16),
                              (uint32_t)l2 | ((uint32_t)l3 << 16));
        *(uint2*)(Ah + row * PAD + c4 * 4) = hp;
        *(uint2*)(Al + row * PAD + c4 * 4) = lp;
    }
    if (tid < D) { c1s[tid] = g_c1[tid]; bos[tid] = bo[tid]; }
    __syncthreads();

    // ---- MMA mainloop (fused 3-term) ----
    const int row0 = wid * 16;
    const int g = lid >> 2, t = lid & 3;
    float acc[16][4];
    #pragma unroll
    for (int n = 0; n < 16; n++) { acc[n][0] = acc[n][1] = acc[n][2] = acc[n][3] = 0.f; }

    const unsigned short* ah0 = Ah + (row0 + g) * PAD + 2 * t;
    const unsigned short* ah1 = Ah + (row0 + g + 8) * PAD + 2 * t;
    const unsigned short* al0 = Al + (row0 + g) * PAD + 2 * t;
    const unsigned short* al1 = Al + (row0 + g + 8) * PAD + 2 * t;
    const unsigned short* bhp = Bh + g * PAD + 2 * t;
    const unsigned short* blp = Bl + g * PAD + 2 * t;

    #pragma unroll
    for (int kk = 0; kk < 8; kk++) {
        const int ko = kk * 16;
        uint32_t h0 = *(const uint32_t*)(ah0 + ko);
        uint32_t h1 = *(const uint32_t*)(ah1 + ko);
        uint32_t h2 = *(const uint32_t*)(ah0 + ko + 8);
        uint32_t h3 = *(const uint32_t*)(ah1 + ko + 8);
        uint32_t l0 = *(const uint32_t*)(al0 + ko);
        uint32_t l1 = *(const uint32_t*)(al1 + ko);
        uint32_t l2 = *(const uint32_t*)(al0 + ko + 8);
        uint32_t l3 = *(const uint32_t*)(al1 + ko + 8);
        #pragma unroll
        for (int n = 0; n < 16; n++) {
            uint32_t bh0 = *(const uint32_t*)(bhp + n * 8 * PAD + ko);
            uint32_t bh1 = *(const uint32_t*)(bhp + n * 8 * PAD + ko + 8);
            uint32_t bl0 = *(const uint32_t*)(blp + n * 8 * PAD + ko);
            uint32_t bl1 = *(const uint32_t*)(blp + n * 8 * PAD + ko + 8);
            asm volatile(
                "mma.sync.aligned.m16n8k16.row.col.f32.bf16.bf16.f32 "
                "{%0,%1,%2,%3}, {%4,%5,%6,%7}, {%8,%9}, {%0,%1,%2,%3};"
                : "+f"(acc[n][0]), "+f"(acc[n][1]), "+f"(acc[n][2]), "+f"(acc[n][3])
                : "r"(h0), "r"(h1), "r"(h2), "r"(h3), "r"(bh0), "r"(bh1));
            asm volatile(
                "mma.sync.aligned.m16n8k16.row.col.f32.bf16.bf16.f32 "
                "{%0,%1,%2,%3}, {%4,%5,%6,%7}, {%8,%9}, {%0,%1,%2,%3};"
                : "+f"(acc[n][0]), "+f"(acc[n][1]), "+f"(acc[n][2]), "+f"(acc[n][3])
                : "r"(l0), "r"(l1), "r"(l2), "r"(l3), "r"(bh0), "r"(bh1));
            asm volatile(
                "mma.sync.aligned.m16n8k16.row.col.f32.bf16.bf16.f32 "
                "{%0,%1,%2,%3}, {%4,%5,%6,%7}, {%8,%9}, {%0,%1,%2,%3};"
                : "+f"(acc[n][0]), "+f"(acc[n][1]), "+f"(acc[n][2]), "+f"(acc[n][3])
                : "r"(h0), "r"(h1), "r"(h2), "r"(h3), "r"(bl0), "r"(bl1));
        }
    }
    __syncthreads();   // done reading tiles; reuse smem as fp32 staging

    // ---- Epilogue: fragments -> SMEM (stride 132 floats), then coalesced masked store ----
    float* Cst = (float*)sm;
    #pragma unroll
    for (int n = 0; n < 16; n++) {
        int c = n * 8 + 2 * t;
        *(float2*)(Cst + (row0 + g) * 132 + c)     = make_float2(acc[n][0], acc[n][1]);
        *(float2*)(Cst + (row0 + g + 8) * 132 + c) = make_float2(acc[n][2], acc[n][3]);
    }
    __syncthreads();
    #pragma unroll
    for (int i = 0; i < 16; i++) {
        int idx = tid + i * 256;
        int row = idx >> 5, c4 = idx & 31;
        int gm = m0 + row;
        if (gm >= V) continue;
        bool msk = g_mask[gm] != 0;
        float4 v = *(const float4*)(Cst + row * 132 + c4 * 4);
        float4 r;
        r.x = msk ? v.x + c1s[c4 * 4 + 0] : bos[c4 * 4 + 0];
        r.y = msk ? v.y + c1s[c4 * 4 + 1] : bos[c4 * 4 + 1];
        r.z = msk ? v.z + c1s[c4 * 4 + 2] : bos[c4 * 4 + 2];
        r.w = msk ? v.w + c1s[c4 * 4 + 3] : bos[c4 * 4 + 3];
        ((float4*)out)[(size_t)gm * 32 + c4] = r;
    }
}

// ---------------- launch ----------------
extern "C" void kernel_launch(void* const* d_in, const int* in_sizes, int n_in,
                              void* d_out, int out_size) {
    const float* node = (const float*)d_in[0];
    const int*   ei   = (const int*)d_in[2];
    const float* Wv   = (const float*)d_in[7];
    const float* bv   = (const float*)d_in[8];
    const float* Wo   = (const float*)d_in[11];
    const float* bo   = (const float*)d_in[12];
    float* out = (float*)d_out;

    const int V = in_sizes[0] / D;
    const int E = in_sizes[2] / 2;

    cudaFuncSetAttribute(k_prep, cudaFuncAttributeMaxDynamicSharedMemorySize, 65536);
    k_prep<<<16 + (MASK_BYTES / 16 + 255) / 256, 256, 65536>>>(Wv, Wo, bv, bo);
    k_mask_scatter<<<(E / 4 + 256) / 256, 256>>>(ei, E);

    const int smem = 4 * BM * PAD * 2;   // 139264 B
    cudaFuncSetAttribute(k_gemm_mma, cudaFuncAttributeMaxDynamicSharedMemorySize, smem);
    k_gemm_mma<<<(V + BM - 1) / BM, 256, smem>>>(node, bo, out, V);
}

// round 8
// speedup vs baseline: 1.2607x; 1.0450x over previous
#include <cuda_runtime.h>
#include <cuda_fp16.h>
#include <cstdint>

#define D 128
#define BM 128
#define PAD 136            // fp16 elems per SMEM row (272B = 68 words, 68%32=4 -> conflict-free)
#define MASK_BYTES 50048   // V rounded up, 3128 int4

// ---------------- device scratch (no allocations allowed) ----------------
__device__ float g_c1[D];                        // b_v @ W_o + b_o
__device__ unsigned char g_mask[MASK_BYTES];     // indeg(v) > 0
__device__ __align__(16) unsigned short g_Bh[D * D];  // B[n][k] = W_vo[k][n], fp16

__device__ __forceinline__ unsigned short f16u(float x) {
    return __half_as_ushort(__float2half_rn(x));
}

// ---------------- kernel 1: prep W_vo (fp16, [n][k]) + c1 + zero mask ----------------
// Blocks 0..15: Wo staged in 64KB smem; block b computes i-rows [8b, 8b+8).
// Blocks 16..28: vectorized mask zero.
__global__ void k_prep(const float* __restrict__ Wv, const float* __restrict__ Wo,
                       const float* __restrict__ bv, const float* __restrict__ bo) {
    extern __shared__ float WoS[];                // [128][128]
    __shared__ float WvS[8 * D];
    const int tid = threadIdx.x;
    const int b = blockIdx.x;
    if (b >= 16) {                                // mask-zero portion
        int idx = (b - 16) * 256 + tid;
        if (idx < MASK_BYTES / 16) ((int4*)g_mask)[idx] = make_int4(0, 0, 0, 0);
        return;
    }
    #pragma unroll
    for (int i = 0; i < 16; i++)
        ((float4*)WoS)[tid + i * 256] = ((const float4*)Wo)[tid + i * 256];
    ((float4*)WvS)[tid] = ((const float4*)(Wv + b * 8 * D))[tid];
    __syncthreads();

    const int il = tid >> 5;                      // warp id = local i row (uniform per warp)
    const int j4 = tid & 31;                      // 4 output cols j4*4..j4*4+3
    float4 acc = make_float4(0.f, 0.f, 0.f, 0.f);
    #pragma unroll 8
    for (int k = 0; k < D; k++) {
        float a = WvS[il * D + k];                // warp-broadcast LDS
        float4 w = ((const float4*)WoS)[k * 32 + j4];   // LDS.128, conflict-free
        acc.x = fmaf(a, w.x, acc.x);
        acc.y = fmaf(a, w.y, acc.y);
        acc.z = fmaf(a, w.z, acc.z);
        acc.w = fmaf(a, w.w, acc.w);
    }
    const int i = b * 8 + il;                     // k-index of W_vo
    g_Bh[(j4 * 4 + 0) * D + i] = f16u(acc.x);     // B[n][k]
    g_Bh[(j4 * 4 + 1) * D + i] = f16u(acc.y);
    g_Bh[(j4 * 4 + 2) * D + i] = f16u(acc.z);
    g_Bh[(j4 * 4 + 3) * D + i] = f16u(acc.w);

    if (b == 0 && il == 0) {
        float4 c = *(const float4*)(bo + j4 * 4);
        #pragma unroll 8
        for (int k = 0; k < D; k++) {
            float bk = bv[k];
            float4 w = ((const float4*)WoS)[k * 32 + j4];
            c.x = fmaf(bk, w.x, c.x);
            c.y = fmaf(bk, w.y, c.y);
            c.z = fmaf(bk, w.z, c.z);
            c.w = fmaf(bk, w.w, c.w);
        }
        *(float4*)(g_c1 + j4 * 4) = c;
    }
}

// ---------------- kernel 2: scatter indeg mask (int4-vectorized, scalar tail) ----------------
__global__ void k_mask_scatter(const int* __restrict__ ei, int E) {
    int t = blockIdx.x * blockDim.x + threadIdx.x;
    int E4 = E >> 2;
    if (t < E4) {
        int4 d = ((const int4*)(ei + E))[t];
        g_mask[d.x] = 1; g_mask[d.y] = 1; g_mask[d.z] = 1; g_mask[d.w] = 1;
    } else if (t == E4) {
        for (int e = E4 * 4; e < E; e++) g_mask[ei[E + e]] = 1;
    }
}

// ---------------- kernel 3: HMMA GEMM (fp16 split, 2-term) ----------------
// out[v,:] = mask[v] ? node[v,:] @ W_vo + c1 : b_o
// A = Ah + Al (fp16 pair, exact to ~2^-22); D = Ah*Bh + Al*Bh; dropped A*Bl ~ 2^-12 rel.
__global__ __launch_bounds__(256, 2)
void k_gemm_mma(const float* __restrict__ A, const float* __restrict__ bo,
                float* __restrict__ out, int V) {
    extern __shared__ __align__(16) unsigned short sm[];
    unsigned short* Ah = sm;                 // [128][PAD]
    unsigned short* Al = sm + BM * PAD;
    unsigned short* Bh = sm + 2 * BM * PAD;  // [128 n][PAD k]
    __shared__ float c1s[D], bos[D];

    const int tid = threadIdx.x;
    const int wid = tid >> 5, lid = tid & 31;
    const int m0 = blockIdx.x * BM;

    // Stage B: 2048 uint4 (128 rows x 16 chunks), coalesced.
    #pragma unroll
    for (int i = 0; i < 8; i++) {
        int idx = tid + i * 256;
        int n = idx >> 4, c = idx & 15;
        *(uint4*)(Bh + n * PAD + c * 8) = ((const uint4*)g_Bh)[idx];
    }
    // Stage A: fp32 -> fp16 hi/lo. 4096 float4, coalesced.
    #pragma unroll
    for (int i = 0; i < 16; i++) {
        int idx = tid + i * 256;
        int row = idx >> 5, c4 = idx & 31;
        int gm = m0 + row;
        float4 v = make_float4(0.f, 0.f, 0.f, 0.f);
        if (gm < V) v = ((const float4*)A)[(size_t)gm * 32 + c4];
        __half h0 = __float2half_rn(v.x), h1 = __float2half_rn(v.y);
        __half h2 = __float2half_rn(v.z), h3 = __float2half_rn(v.w);
        uint2 hp = make_uint2((uint32_t)__half_as_ushort(h0) | ((uint32_t)__half_as_ushort(h1) << 16),
                              (uint32_t)__half_as_ushort(h2) | ((uint32_t)__half_as_ushort(h3) << 16));
        __half l0 = __float2half_rn(v.x - __half2float(h0));
        __half l1 = __float2half_rn(v.y - __half2float(h1));
        __half l2 = __float2half_rn(v.z - __half2float(h2));
        __half l3 = __float2half_rn(v.w - __half2float(h3));
        uint2 lp = make_uint2((uint32_t)__half_as_ushort(l0) | ((uint32_t)__half_as_ushort(l1) << 16),
                              (uint32_t)__half_as_ushort(l2) | ((uint32_t)__half_as_ushort(l3) << 16));
        *(uint2*)(Ah + row * PAD + c4 * 4) = hp;
        *(uint2*)(Al + row * PAD + c4 * 4) = lp;
    }
    if (tid < D) { c1s[tid] = g_c1[tid]; bos[tid] = bo[tid]; }
    __syncthreads();

    // ---- MMA mainloop: 8 kk x 16 n x 2 MMA ----
    const int row0 = wid * 16;
    const int g = lid >> 2, t = lid & 3;
    float acc[16][4];
    #pragma unroll
    for (int n = 0; n < 16; n++) { acc[n][0] = acc[n][1] = acc[n][2] = acc[n][3] = 0.f; }

    const unsigned short* ah0 = Ah + (row0 + g) * PAD + 2 * t;
    const unsigned short* ah1 = Ah + (row0 + g + 8) * PAD + 2 * t;
    const unsigned short* al0 = Al + (row0 + g) * PAD + 2 * t;
    const unsigned short* al1 = Al + (row0 + g + 8) * PAD + 2 * t;
    const unsigned short* bhp = Bh + g * PAD + 2 * t;

    #pragma unroll
    for (int kk = 0; kk < 8; kk++) {
        const int ko = kk * 16;
        uint32_t h0 = *(const uint32_t*)(ah0 + ko);
        uint32_t h1 = *(const uint32_t*)(ah1 + ko);
        uint32_t h2 = *(const uint32_t*)(ah0 + ko + 8);
        uint32_t h3 = *(const uint32_t*)(ah1 + ko + 8);
        uint32_t l0 = *(const uint32_t*)(al0 + ko);
        uint32_t l1 = *(const uint32_t*)(al1 + ko);
        uint32_t l2 = *(const uint32_t*)(al0 + ko + 8);
        uint32_t l3 = *(const uint32_t*)(al1 + ko + 8);
        #pragma unroll
        for (int n = 0; n < 16; n++) {
            uint32_t b0 = *(const uint32_t*)(bhp + n * 8 * PAD + ko);
            uint32_t b1 = *(const uint32_t*)(bhp + n * 8 * PAD + ko + 8);
            asm volatile(
                "mma.sync.aligned.m16n8k16.row.col.f32.f16.f16.f32 "
                "{%0,%1,%2,%3}, {%4,%5,%6,%7}, {%8,%9}, {%0,%1,%2,%3};"
                : "+f"(acc[n][0]), "+f"(acc[n][1]), "+f"(acc[n][2]), "+f"(acc[n][3])
                : "r"(h0), "r"(h1), "r"(h2), "r"(h3), "r"(b0), "r"(b1));
            asm volatile(
                "mma.sync.aligned.m16n8k16.row.col.f32.f16.f16.f32 "
                "{%0,%1,%2,%3}, {%4,%5,%6,%7}, {%8,%9}, {%0,%1,%2,%3};"
                : "+f"(acc[n][0]), "+f"(acc[n][1]), "+f"(acc[n][2]), "+f"(acc[n][3])
                : "r"(l0), "r"(l1), "r"(l2), "r"(l3), "r"(b0), "r"(b1));
        }
    }
    __syncthreads();   // done reading tiles; reuse smem as fp32 staging

    // ---- Epilogue: fragments -> SMEM (stride 132 floats), coalesced masked store ----
    float* Cst = (float*)sm;
    #pragma unroll
    for (int n = 0; n < 16; n++) {
        int c = n * 8 + 2 * t;
        *(float2*)(Cst + (row0 + g) * 132 + c)     = make_float2(acc[n][0], acc[n][1]);
        *(float2*)(Cst + (row0 + g + 8) * 132 + c) = make_float2(acc[n][2], acc[n][3]);
    }
    __syncthreads();
    #pragma unroll
    for (int i = 0; i < 16; i++) {
        int idx = tid + i * 256;
        int row = idx >> 5, c4 = idx & 31;
        int gm = m0 + row;
        if (gm >= V) continue;
        bool msk = g_mask[gm] != 0;
        float4 v = *(const float4*)(Cst + row * 132 + c4 * 4);
        float4 r;
        r.x = msk ? v.x + c1s[c4 * 4 + 0] : bos[c4 * 4 + 0];
        r.y = msk ? v.y + c1s[c4 * 4 + 1] : bos[c4 * 4 + 1];
        r.z = msk ? v.z + c1s[c4 * 4 + 2] : bos[c4 * 4 + 2];
        r.w = msk ? v.w + c1s[c4 * 4 + 3] : bos[c4 * 4 + 3];
        ((float4*)out)[(size_t)gm * 32 + c4] = r;
    }
}

// ---------------- launch ----------------
extern "C" void kernel_launch(void* const* d_in, const int* in_sizes, int n_in,
                              void* d_out, int out_size) {
    const float* node = (const float*)d_in[0];
    const int*   ei   = (const int*)d_in[2];
    const float* Wv   = (const float*)d_in[7];
    const float* bv   = (const float*)d_in[8];
    const float* Wo   = (const float*)d_in[11];
    const float* bo   = (const float*)d_in[12];
    float* out = (float*)d_out;

    const int V = in_sizes[0] / D;
    const int E = in_sizes[2] / 2;

    cudaFuncSetAttribute(k_prep, cudaFuncAttributeMaxDynamicSharedMemorySize, 65536);
    k_prep<<<16 + (MASK_BYTES / 16 + 255) / 256, 256, 65536>>>(Wv, Wo, bv, bo);
    k_mask_scatter<<<(E / 4 + 256) / 256, 256>>>(ei, E);

    const int smem = 3 * BM * PAD * 2;   // 104448 B -> 2 CTAs/SM
    cudaFuncSetAttribute(k_gemm_mma, cudaFuncAttributeMaxDynamicSharedMemorySize, smem);
    k_gemm_mma<<<(V + BM - 1) / BM, 256, smem>>>(node, bo, out, V);
}